// round 6
// baseline (speedup 1.0000x reference)
#include <cuda_runtime.h>

#define TDIM 512
#define NREC 256
#define NIN 10
#define NOUT 3
#define BATCH 1024
#define ROWS 8
#define RG 4                // rows per row-group
#define NB (BATCH/ROWS)     // 128 blocks
#define NT 256              // 8 warps, 2/SMSP; 2 row-groups x 128 threads
#define HALF 128
#define JS 176              // j rows cached in SMEM per column
#define WPAD 180            // padded row: conflict-free LDS.128, 16B aligned
#define NSTREAM ((NREC-JS)/4)   // 20 packs of 4 j streamed from L2

typedef unsigned long long u64;

__device__ ulonglong2 g_Wst[NSTREAM * NREC];   // [kb][c]: W_rec[c][176+4kb..+3], 80 KB
__device__ float g_l2p[NB];
__device__ unsigned int g_ctr;

static __device__ __forceinline__ u64 pk(float a, float b){
    u64 r; asm("mov.b64 %0,{%1,%2};":"=l"(r):"f"(a),"f"(b)); return r;
}
static __device__ __forceinline__ u64 fm2(u64 a, u64 b, u64 c){
    u64 d; asm("fma.rn.f32x2 %0,%1,%2,%3;":"=l"(d):"l"(a),"l"(b),"l"(c)); return d;
}
static __device__ __forceinline__ float2 up(u64 v){
    float2 f; asm("mov.b64 {%0,%1},%2;":"=f"(f.x),"=f"(f.y):"l"(v)); return f;
}

__global__ void prep_kernel(const float* __restrict__ W){
    int c = threadIdx.x;   // 256 threads
    const ulonglong2* row = (const ulonglong2*)(W + c * NREC);
    #pragma unroll
    for (int k = 0; k < NSTREAM; k++)
        g_Wst[k * NREC + c] = row[JS/4 + k];
}

__global__ __launch_bounds__(NT, 1)
void rnn_kernel(const float* __restrict__ x,
                const float* __restrict__ noise,
                const float* __restrict__ W_in,
                const float* __restrict__ W_rec,
                const float* __restrict__ W_out,
                const float* __restrict__ b_out,
                const float* __restrict__ bias,
                float* __restrict__ out, int out_size)
{
    extern __shared__ float sm[];
    float* Wsm = sm;                          // [256 c][WPAD] j<176, 180 KB
    float* rT  = Wsm + NREC * WPAD;           // [2][ROWS][NREC] double-buffered
    float* WoS = rT + 2 * ROWS * NREC;        // [3][256]
    float* xb  = WoS + NOUT * NREC;           // [2][ROWS][12]

    const int tid = threadIdx.x;
    const int b0  = blockIdx.x * ROWS;
    const int g   = tid >> 7;                 // row-group: rows 4g..4g+3
    const int t   = tid & (HALF - 1);
    const int ro  = g * RG;
    const int c0  = t;
    const int c1  = t + HALF;

    // ---- init SMEM ----
    for (int idx = tid; idx < NREC * JS; idx += NT){
        int cc = idx / JS, j = idx - cc * JS;
        Wsm[cc * WPAD + j] = W_rec[cc * NREC + j];
    }
    for (int idx = tid; idx < 2 * ROWS * NREC; idx += NT) rT[idx] = 0.f;
    for (int idx = tid; idx < NOUT * NREC; idx += NT) WoS[idx] = W_out[idx];
    if (tid < ROWS * NIN){
        int i = tid / NIN, k = tid % NIN;
        xb[i * 12 + k] = x[(size_t)(b0 + i) * TDIM * NIN + k];   // t=0 into buf 0
    }

    float win0[NIN], win1[NIN];
    #pragma unroll
    for (int k = 0; k < NIN; k++){
        win0[k] = W_in[c0 * NIN + k];
        win1[k] = W_in[c1 * NIN + k];
    }
    const float bs0 = bias[c0], bs1 = bias[c1];
    const float bo0 = b_out[0], bo1 = b_out[1], bo2 = b_out[2];

    float r0[RG], r1[RG];
    #pragma unroll
    for (int i = 0; i < RG; i++){ r0[i] = 0.f; r1[i] = 0.f; }

    float nz0[RG], nz1[RG];
    #pragma unroll
    for (int i = 0; i < RG; i++){
        size_t nb = (size_t)(b0 + ro + i) * TDIM * NREC;
        nz0[i] = noise[nb + c0];
        nz1[i] = noise[nb + c1];
    }
    double l2d = 0.0;
    __syncthreads();

    const int wid = tid >> 5, lane = tid & 31;

    const ulonglong2* __restrict__ wA0 = (const ulonglong2*)(Wsm + c0 * WPAD);
    const ulonglong2* __restrict__ wA1 = (const ulonglong2*)(Wsm + c1 * WPAD);
    const ulonglong2* __restrict__ gw  = g_Wst;

    for (int ts = 0; ts < TDIM; ts++){
        const int cur = ts & 1, nxt = cur ^ 1;
        const float* rTc = rT + cur * ROWS * NREC;
        float*       rTn = rT + nxt * ROWS * NREC;
        const float* xbc = xb + cur * 96;
        float*       xbn = xb + nxt * 96;
        const ulonglong2* __restrict__ rr = (const ulonglong2*)rTc;  // [ROWS][64]

        // u = bias + noise + x @ W_in^T  for my 4 rows x 2 cols
        float u0[RG], u1[RG];
        #pragma unroll
        for (int i = 0; i < RG; i++){ u0[i] = bs0 + nz0[i]; u1[i] = bs1 + nz1[i]; }
        #pragma unroll
        for (int i = 0; i < RG; i++){
            #pragma unroll
            for (int k = 0; k < NIN; k++){
                float xv = xbc[(ro + i) * 12 + k];
                u0[i] = fmaf(xv, win0[k], u0[i]);
                u1[i] = fmaf(xv, win1[k], u1[i]);
            }
        }
        // prefetch next-step noise (hidden under GEMM)
        {
            int tn = (ts + 1 < TDIM) ? ts + 1 : ts;
            #pragma unroll
            for (int i = 0; i < RG; i++){
                size_t nb = ((size_t)(b0 + ro + i) * TDIM + tn) * NREC;
                nz0[i] = noise[nb + c0];
                nz1[i] = noise[nb + c1];
            }
        }

        u64 a0[RG], a1[RG];
        #pragma unroll
        for (int i = 0; i < RG; i++){ a0[i] = pk(u0[i], 0.f); a1[i] = pk(u1[i], 0.f); }

        // ---- phase B first: j in [176,256), weights via LDG.128 (loads fly early) ----
        #pragma unroll 5
        for (int kb = 0; kb < NSTREAM; kb++){
            ulonglong2 w0 = gw[kb * NREC + c0];
            ulonglong2 w1 = gw[kb * NREC + c1];
            #pragma unroll
            for (int i = 0; i < RG; i++){
                ulonglong2 rv = rr[(ro + i) * 64 + JS/4 + kb];
                a0[i] = fm2(rv.x, w0.x, a0[i]);
                a0[i] = fm2(rv.y, w0.y, a0[i]);
                a1[i] = fm2(rv.x, w1.x, a1[i]);
                a1[i] = fm2(rv.y, w1.y, a1[i]);
            }
        }
        // ---- phase A: j in [0,176), weights from SMEM ----
        #pragma unroll 4
        for (int jb = 0; jb < JS/4; jb++){
            ulonglong2 w0 = wA0[jb];
            ulonglong2 w1 = wA1[jb];
            #pragma unroll
            for (int i = 0; i < RG; i++){
                ulonglong2 rv = rr[(ro + i) * 64 + jb];
                a0[i] = fm2(rv.x, w0.x, a0[i]);
                a0[i] = fm2(rv.y, w0.y, a0[i]);
                a1[i] = fm2(rv.x, w1.x, a1[i]);
                a1[i] = fm2(rv.y, w1.y, a1[i]);
            }
        }

        // r_new = 0.8 r + 0.2 relu(v);  v = .x + .y   (my 4 rows, 2 cols)
        float ssum = 0.f;
        #pragma unroll
        for (int i = 0; i < RG; i++){
            float2 v0 = up(a0[i]);
            float2 v1 = up(a1[i]);
            float vv0 = v0.x + v0.y;
            float vv1 = v1.x + v1.y;
            r0[i] = 0.8f * r0[i] + 0.2f * fmaxf(vv0, 0.f);
            r1[i] = 0.8f * r1[i] + 0.2f * fmaxf(vv1, 0.f);
            rTn[(ro + i) * NREC + c0] = r0[i];
            rTn[(ro + i) * NREC + c1] = r1[i];
            ssum = fmaf(r0[i], r0[i], ssum);
            ssum = fmaf(r1[i], r1[i], ssum);
        }
        l2d += (double)ssum;

        // prefetch next x tile
        if (tid < ROWS * NIN){
            int i = tid / NIN, k = tid % NIN;
            int tn = (ts + 1 < TDIM) ? ts + 1 : ts;
            xbn[i * 12 + k] = x[((size_t)(b0 + i) * TDIM + tn) * NIN + k];
        }

        __syncthreads();   // single barrier per step: rTn + xbn published

        // z = r_new @ W_out^T + b_out ; warp w -> batch row w
        {
            float z0 = 0.f, z1 = 0.f, z2 = 0.f;
            #pragma unroll
            for (int q = 0; q < NREC/32; q++){
                int jj = lane + 32 * q;
                float ra = rTn[wid * NREC + jj];
                z0 = fmaf(ra, WoS[jj],          z0);
                z1 = fmaf(ra, WoS[NREC + jj],   z1);
                z2 = fmaf(ra, WoS[2*NREC + jj], z2);
            }
            #pragma unroll
            for (int off = 16; off; off >>= 1){
                z0 += __shfl_down_sync(~0u, z0, off);
                z1 += __shfl_down_sync(~0u, z1, off);
                z2 += __shfl_down_sync(~0u, z2, off);
            }
            if (lane == 0){
                size_t ob = ((size_t)(b0 + wid) * TDIM + ts) * NOUT;
                out[ob+0] = z0 + bo0; out[ob+1] = z1 + bo1; out[ob+2] = z2 + bo2;
            }
        }
    }

    // ---- deterministic l2 reduction, last-block finalization ----
    __syncthreads();
    double* dd = (double*)sm;
    dd[tid] = l2d;
    __syncthreads();
    if (tid == 0){
        double s = 0.0;
        #pragma unroll 8
        for (int i = 0; i < NT; i++) s += dd[i];
        g_l2p[blockIdx.x] = (float)s;
        __threadfence();
        unsigned int old = atomicInc(&g_ctr, NB - 1);
        if (old == NB - 1){
            __threadfence();
            double tot = 0.0;
            for (int i = 0; i < NB; i++) tot += (double)g_l2p[i];
            out[out_size - 1] = (float)(tot / ((double)TDIM * BATCH * NREC));
        }
    }
}

extern "C" void kernel_launch(void* const* d_in, const int* in_sizes, int n_in,
                              void* d_out, int out_size)
{
    const float* x     = (const float*)d_in[0];
    const float* noise = (const float*)d_in[1];
    const float* W_in  = (const float*)d_in[2];
    const float* W_rec = (const float*)d_in[3];
    const float* W_out = (const float*)d_in[4];
    const float* b_out = (const float*)d_in[5];
    const float* bias  = (const float*)d_in[6];
    float* out = (float*)d_out;

    size_t smem = (size_t)(NREC*WPAD + 2*ROWS*NREC + NOUT*NREC + 2*96) * sizeof(float);
    cudaFuncSetAttribute(rnn_kernel, cudaFuncAttributeMaxDynamicSharedMemorySize, (int)smem);

    prep_kernel<<<1, 256>>>(W_rec);
    rnn_kernel<<<NB, NT, smem>>>(x, noise, W_in, W_rec, W_out, b_out, bias, out, out_size);
}

// round 7
// speedup vs baseline: 1.0451x; 1.0451x over previous
#include <cuda_runtime.h>

#define TDIM 512
#define NREC 256
#define NIN 10
#define NOUT 3
#define BATCH 1024
#define ROWS 8
#define RG 4                // rows per row-group
#define NB (BATCH/ROWS)     // 128 blocks
#define NT 256              // 8 warps, 2/SMSP; 2 row-groups x 128 threads
#define HALF 128
#define JS 128              // j rows cached in SMEM per column
#define WPAD 132            // padded row: conflict-free LDS.128
#define NSTREAM (JS/4)      // 32 packs of 4 j streamed from L2

typedef unsigned long long u64;

__device__ ulonglong2 g_Wst[NSTREAM * NREC];   // [kb][c]: W_rec[c][128+4kb..+3], 128 KB
__device__ float g_l2p[NB];
__device__ unsigned int g_ctr;

static __device__ __forceinline__ u64 pk(float a, float b){
    u64 r; asm("mov.b64 %0,{%1,%2};":"=l"(r):"f"(a),"f"(b)); return r;
}
static __device__ __forceinline__ u64 fm2(u64 a, u64 b, u64 c){
    u64 d; asm("fma.rn.f32x2 %0,%1,%2,%3;":"=l"(d):"l"(a),"l"(b),"l"(c)); return d;
}
static __device__ __forceinline__ float2 up(u64 v){
    float2 f; asm("mov.b64 {%0,%1},%2;":"=f"(f.x),"=f"(f.y):"l"(v)); return f;
}

__global__ void prep_kernel(const float* __restrict__ W){
    int c = threadIdx.x;   // 256 threads
    const ulonglong2* row = (const ulonglong2*)(W + c * NREC);
    #pragma unroll
    for (int k = 0; k < NSTREAM; k++)
        g_Wst[k * NREC + c] = row[JS/4 + k];
}

__global__ __launch_bounds__(NT, 1)
void rnn_kernel(const float* __restrict__ x,
                const float* __restrict__ noise,
                const float* __restrict__ W_in,
                const float* __restrict__ W_rec,
                const float* __restrict__ W_out,
                const float* __restrict__ b_out,
                const float* __restrict__ bias,
                float* __restrict__ out, int out_size)
{
    extern __shared__ float sm[];
    float* Wsm = sm;                          // [256 c][WPAD] j<128, 135 KB
    float* rT  = Wsm + NREC * WPAD;           // [2][ROWS][NREC] double-buffered
    float* WoS = rT + 2 * ROWS * NREC;        // [3][256]
    float* xb  = WoS + NOUT * NREC;           // [2][ROWS][12]

    const int tid = threadIdx.x;
    const int b0  = blockIdx.x * ROWS;
    const int g   = tid >> 7;                 // row-group: rows 4g..4g+3
    const int t   = tid & (HALF - 1);
    const int ro  = g * RG;
    const int c0  = t;
    const int c1  = t + HALF;

    // ---- init SMEM ----
    for (int idx = tid; idx < NREC * JS; idx += NT){
        int cc = idx >> 7, j = idx & (JS - 1);
        Wsm[cc * WPAD + j] = W_rec[cc * NREC + j];
    }
    for (int idx = tid; idx < 2 * ROWS * NREC; idx += NT) rT[idx] = 0.f;
    for (int idx = tid; idx < NOUT * NREC; idx += NT) WoS[idx] = W_out[idx];
    if (tid < ROWS * NIN){
        int i = tid / NIN, k = tid % NIN;
        xb[i * 12 + k] = x[(size_t)(b0 + i) * TDIM * NIN + k];   // t=0 into buf 0
    }

    float win0[NIN], win1[NIN];
    #pragma unroll
    for (int k = 0; k < NIN; k++){
        win0[k] = W_in[c0 * NIN + k];
        win1[k] = W_in[c1 * NIN + k];
    }
    const float bs0 = bias[c0], bs1 = bias[c1];
    const float bo0 = b_out[0], bo1 = b_out[1], bo2 = b_out[2];

    float r0[RG], r1[RG];
    #pragma unroll
    for (int i = 0; i < RG; i++){ r0[i] = 0.f; r1[i] = 0.f; }

    float nz0[RG], nz1[RG];
    #pragma unroll
    for (int i = 0; i < RG; i++){
        size_t nb = (size_t)(b0 + ro + i) * TDIM * NREC;
        nz0[i] = noise[nb + c0];
        nz1[i] = noise[nb + c1];
    }
    double l2d = 0.0;
    __syncthreads();

    const int wid = tid >> 5, lane = tid & 31;

    const ulonglong2* __restrict__ wA0 = (const ulonglong2*)(Wsm + c0 * WPAD);
    const ulonglong2* __restrict__ wA1 = (const ulonglong2*)(Wsm + c1 * WPAD);
    const ulonglong2* __restrict__ gw  = g_Wst;

    for (int ts = 0; ts < TDIM; ts++){
        const int cur = ts & 1, nxt = cur ^ 1;
        const float* rTc = rT + cur * ROWS * NREC;
        float*       rTn = rT + nxt * ROWS * NREC;
        const float* xbc = xb + cur * 96;
        float*       xbn = xb + nxt * 96;
        const ulonglong2* __restrict__ rr = (const ulonglong2*)rTc;  // [ROWS][64]

        // next-step noise prefetch: issue FIRST so DRAM latency hides under GEMM
        float pn0[RG], pn1[RG];
        {
            int tn = (ts + 1 < TDIM) ? ts + 1 : ts;
            #pragma unroll
            for (int i = 0; i < RG; i++){
                size_t nb = ((size_t)(b0 + ro + i) * TDIM + tn) * NREC;
                pn0[i] = noise[nb + c0];
                pn1[i] = noise[nb + c1];
            }
        }

        // accumulators start at zero; u is added in the tail (no serial head)
        u64 a0[RG], a1[RG];
        #pragma unroll
        for (int i = 0; i < RG; i++){ a0[i] = pk(0.f, 0.f); a1[i] = pk(0.f, 0.f); }

        // ---- fused loop: SMEM weights (j=4*it) + L2-streamed weights (j=128+4*it)
        //      keeps the smem crossbar and the LDG path busy CONCURRENTLY ----
        #pragma unroll 4
        for (int it = 0; it < NSTREAM; it++){
            ulonglong2 wg0 = gw[it * NREC + c0];         // LDG.128
            ulonglong2 wg1 = gw[it * NREC + c1];
            ulonglong2 ws0 = wA0[it];                    // LDS.128
            ulonglong2 ws1 = wA1[it];
            #pragma unroll
            for (int i = 0; i < RG; i++){
                ulonglong2 rva = rr[(ro + i) * 64 + it];            // broadcast
                ulonglong2 rvb = rr[(ro + i) * 64 + JS/4 + it];     // broadcast
                a0[i] = fm2(rva.x, ws0.x, a0[i]);
                a0[i] = fm2(rva.y, ws0.y, a0[i]);
                a1[i] = fm2(rva.x, ws1.x, a1[i]);
                a1[i] = fm2(rva.y, ws1.y, a1[i]);
                a0[i] = fm2(rvb.x, wg0.x, a0[i]);
                a0[i] = fm2(rvb.y, wg0.y, a0[i]);
                a1[i] = fm2(rvb.x, wg1.x, a1[i]);
                a1[i] = fm2(rvb.y, wg1.y, a1[i]);
            }
        }

        // u = bias + noise + x @ W_in^T   (overlaps with GEMM tail latency)
        float u0[RG], u1[RG];
        #pragma unroll
        for (int i = 0; i < RG; i++){ u0[i] = bs0 + nz0[i]; u1[i] = bs1 + nz1[i]; }
        #pragma unroll
        for (int i = 0; i < RG; i++){
            #pragma unroll
            for (int k = 0; k < NIN; k++){
                float xv = xbc[(ro + i) * 12 + k];
                u0[i] = fmaf(xv, win0[k], u0[i]);
                u1[i] = fmaf(xv, win1[k], u1[i]);
            }
        }
        #pragma unroll
        for (int i = 0; i < RG; i++){ nz0[i] = pn0[i]; nz1[i] = pn1[i]; }

        // r_new = 0.8 r + 0.2 relu(gemm + u)
        float ssum = 0.f;
        #pragma unroll
        for (int i = 0; i < RG; i++){
            float2 v0 = up(a0[i]);
            float2 v1 = up(a1[i]);
            float vv0 = (v0.x + v0.y) + u0[i];
            float vv1 = (v1.x + v1.y) + u1[i];
            r0[i] = 0.8f * r0[i] + 0.2f * fmaxf(vv0, 0.f);
            r1[i] = 0.8f * r1[i] + 0.2f * fmaxf(vv1, 0.f);
            rTn[(ro + i) * NREC + c0] = r0[i];
            rTn[(ro + i) * NREC + c1] = r1[i];
            ssum = fmaf(r0[i], r0[i], ssum);
            ssum = fmaf(r1[i], r1[i], ssum);
        }
        l2d += (double)ssum;

        // prefetch next x tile
        if (tid < ROWS * NIN){
            int i = tid / NIN, k = tid % NIN;
            int tn = (ts + 1 < TDIM) ? ts + 1 : ts;
            xbn[i * 12 + k] = x[((size_t)(b0 + i) * TDIM + tn) * NIN + k];
        }

        __syncthreads();   // single barrier per step

        // z = r_new @ W_out^T + b_out ; warp w -> batch row w
        {
            float z0 = 0.f, z1 = 0.f, z2 = 0.f;
            #pragma unroll
            for (int q = 0; q < NREC/32; q++){
                int jj = lane + 32 * q;
                float ra = rTn[wid * NREC + jj];
                z0 = fmaf(ra, WoS[jj],          z0);
                z1 = fmaf(ra, WoS[NREC + jj],   z1);
                z2 = fmaf(ra, WoS[2*NREC + jj], z2);
            }
            #pragma unroll
            for (int off = 16; off; off >>= 1){
                z0 += __shfl_down_sync(~0u, z0, off);
                z1 += __shfl_down_sync(~0u, z1, off);
                z2 += __shfl_down_sync(~0u, z2, off);
            }
            if (lane == 0){
                size_t ob = ((size_t)(b0 + wid) * TDIM + ts) * NOUT;
                out[ob+0] = z0 + bo0; out[ob+1] = z1 + bo1; out[ob+2] = z2 + bo2;
            }
        }
    }

    // ---- deterministic l2 reduction, last-block finalization ----
    __syncthreads();
    double* dd = (double*)sm;
    dd[tid] = l2d;
    __syncthreads();
    if (tid == 0){
        double s = 0.0;
        #pragma unroll 8
        for (int i = 0; i < NT; i++) s += dd[i];
        g_l2p[blockIdx.x] = (float)s;
        __threadfence();
        unsigned int old = atomicInc(&g_ctr, NB - 1);
        if (old == NB - 1){
            __threadfence();
            double tot = 0.0;
            for (int i = 0; i < NB; i++) tot += (double)g_l2p[i];
            out[out_size - 1] = (float)(tot / ((double)TDIM * BATCH * NREC));
        }
    }
}

extern "C" void kernel_launch(void* const* d_in, const int* in_sizes, int n_in,
                              void* d_out, int out_size)
{
    const float* x     = (const float*)d_in[0];
    const float* noise = (const float*)d_in[1];
    const float* W_in  = (const float*)d_in[2];
    const float* W_rec = (const float*)d_in[3];
    const float* W_out = (const float*)d_in[4];
    const float* b_out = (const float*)d_in[5];
    const float* bias  = (const float*)d_in[6];
    float* out = (float*)d_out;

    size_t smem = (size_t)(NREC*WPAD + 2*ROWS*NREC + NOUT*NREC + 2*96) * sizeof(float);
    cudaFuncSetAttribute(rnn_kernel, cudaFuncAttributeMaxDynamicSharedMemorySize, (int)smem);

    prep_kernel<<<1, 256>>>(W_rec);
    rnn_kernel<<<NB, NT, smem>>>(x, noise, W_in, W_rec, W_out, b_out, bias, out, out_size);
}